// round 8
// baseline (speedup 1.0000x reference)
#include <cuda_runtime.h>
#include <cuda_fp16.h>

// DilationLayerExtSE: out[b,c,h,w] = max_{di,dj in 5x5}( zeropad2(x)[h+di,w+dj] + w[b,c,di,dj] ) + bias[b,c]
// x [8,128,128,128] f32. stride=1, pad=2.
//
// R8: R7 (fp16 HADD2/HMAX2 tree fold, 8 rows x 8 cols/thread, 2048x128)
//     + SOFTWARE-PIPELINED row loads: iteration t issues the 4 LDGs for
//     input row t+1 into the alternate buffer, then converts/folds row t
//     (loaded one full iteration earlier) -> load latency hidden behind
//     ~200 issue slots of fold work instead of stalling the cvt chain.
//   Max in fp16; bias added in fp32 at the store.
//   Zero padding: OOB gives x=0 (reference zero-pads BEFORE +w).

#define H_DIM 128
#define W_DIM 128

__device__ __forceinline__ unsigned h2u(__half2 v) {
    return *reinterpret_cast<unsigned*>(&v);
}
__device__ __forceinline__ __half2 u2h(unsigned v) {
    return *reinterpret_cast<__half2*>(&v);
}
// (a.y, b.x) — one PRMT
__device__ __forceinline__ __half2 h2shift(__half2 a, __half2 b) {
    return u2h(__byte_perm(h2u(a), h2u(b), 0x5432));
}

__global__ __launch_bounds__(128)
void dilation_kernel(const float* __restrict__ x,
                     const float* __restrict__ wgt,
                     const float* __restrict__ bias,
                     float* __restrict__ out) {
    const int blk   = blockIdx.x;            // 0..2047
    const int plane = blk >> 1;              // b*C + c
    const int half  = blk & 1;
    const int tid   = threadIdx.x;
    const int cg    = tid & 15;              // column group 0..15 (8 cols)
    const int strip = tid >> 4;              // 0..7 (8 rows each)
    const int colbase = cg << 3;
    const int r0      = half * 64 + strip * 8;

    const float* __restrict__ xp = x   + (size_t)plane * (H_DIM * W_DIM) + colbase;
    float*       __restrict__ op = out + (size_t)plane * (H_DIM * W_DIM) + colbase;
    const float* __restrict__ wp = wgt + plane * 25;
    const float b = __ldg(&bias[plane]);

    // broadcast-pair fp16 weights (bias added in fp32 at store)
    __half2 wh[25];
#pragma unroll
    for (int k = 0; k < 25; ++k) wh[k] = __float2half2_rn(__ldg(&wp[k]));

    const bool hasA = (cg >= 1);
    const bool hasC = (cg <= 14);

    // double-buffered raw row (12 floats = x at cols colbase-2 .. colbase+9)
    float rowf[2][12];

#define LOADROW(rowidx, buf) do {                                            \
    const int rr_ = (rowidx);                                                \
    float* d_ = (buf);                                                       \
    _Pragma("unroll")                                                        \
    for (int i_ = 0; i_ < 12; ++i_) d_[i_] = 0.f;                            \
    if ((unsigned)rr_ < (unsigned)H_DIM) {                                   \
        const float* rp_ = xp + rr_ * W_DIM;                                 \
        if (hasA) {                                                          \
            const float2 A_ = __ldg(reinterpret_cast<const float2*>(rp_ - 2)); \
            d_[0] = A_.x; d_[1] = A_.y;                                      \
        }                                                                    \
        const float4 B0_ = __ldg(reinterpret_cast<const float4*>(rp_));      \
        const float4 B1_ = __ldg(reinterpret_cast<const float4*>(rp_ + 4));  \
        d_[2] = B0_.x; d_[3] = B0_.y; d_[4] = B0_.z; d_[5] = B0_.w;          \
        d_[6] = B1_.x; d_[7] = B1_.y; d_[8] = B1_.z; d_[9] = B1_.w;          \
        if (hasC) {                                                          \
            const float2 C_ = __ldg(reinterpret_cast<const float2*>(rp_ + 8)); \
            d_[10] = C_.x; d_[11] = C_.y;                                    \
        }                                                                    \
    }                                                                        \
} while (0)

    __half2 acc[5][4];                       // 5 in-flight output rows x 4 pairs

    // prologue: load row t=0
    LOADROW(r0 - 2, rowf[0]);

#pragma unroll
    for (int t = 0; t < 12; ++t) {
        // issue next row's loads first (latency hidden behind this fold)
        if (t < 11) LOADROW(r0 - 1 + t, rowf[(t + 1) & 1]);

        const float* rf = rowf[t & 1];

        // pairs[j] = (rf[j], rf[j+1]) as half2, j = 0..10
        __half2 pairs[11];
#pragma unroll
        for (int i = 0; i < 6; ++i)
            pairs[2 * i] = __floats2half2_rn(rf[2 * i], rf[2 * i + 1]);
#pragma unroll
        for (int i = 0; i < 5; ++i)
            pairs[2 * i + 1] = h2shift(pairs[2 * i], pairs[2 * i + 2]);

        // Fold into in-flight outputs oh = t-di (weight row di), tree max.
#pragma unroll
        for (int di = 0; di < 5; ++di) {
            const int oh = t - di;
            if (oh < 0 || oh > 7) continue;   // compile-time pruned
            __half2* a = acc[oh % 5];
            const __half2* w = &wh[di * 5];
#pragma unroll
            for (int p = 0; p < 4; ++p) {
                const __half2 m01 = __hmax2(__hadd2(pairs[2 * p],     w[0]),
                                            __hadd2(pairs[2 * p + 1], w[1]));
                const __half2 m23 = __hmax2(__hadd2(pairs[2 * p + 2], w[2]),
                                            __hadd2(pairs[2 * p + 3], w[3]));
                const __half2 m4  = __hadd2(pairs[2 * p + 4], w[4]);
                const __half2 m   = __hmax2(__hmax2(m01, m23), m4);
                a[p] = (di == 0) ? m : __hmax2(a[p], m);
            }
        }

        // Output row oh = t-4 complete: convert, add bias in fp32, store.
        if (t >= 4) {
            const int oh = t - 4;
            const __half2* a = acc[oh % 5];
            float* orow = op + (size_t)(r0 + oh) * W_DIM;
            const float4 lo = make_float4(__low2float(a[0]) + b,
                                          __high2float(a[0]) + b,
                                          __low2float(a[1]) + b,
                                          __high2float(a[1]) + b);
            const float4 hi = make_float4(__low2float(a[2]) + b,
                                          __high2float(a[2]) + b,
                                          __low2float(a[3]) + b,
                                          __high2float(a[3]) + b);
            *reinterpret_cast<float4*>(orow)     = lo;
            *reinterpret_cast<float4*>(orow + 4) = hi;
        }
    }
#undef LOADROW
}

extern "C" void kernel_launch(void* const* d_in, const int* in_sizes, int n_in,
                              void* d_out, int out_size) {
    (void)in_sizes; (void)n_in; (void)out_size;
    const float* x    = (const float*)d_in[0];   // [8,128,128,128]
    const float* wgt  = (const float*)d_in[1];   // [8,128,5,5]
    const float* bias = (const float*)d_in[2];   // [8,128]
    float* out = (float*)d_out;                  // [8,128,128,128]

    dilation_kernel<<<2048, 128>>>(x, wgt, bias, out);
}

// round 9
// speedup vs baseline: 1.0218x; 1.0218x over previous
#include <cuda_runtime.h>
#include <cuda_fp16.h>

// DilationLayerExtSE: out[b,c,h,w] = max_{di,dj in 5x5}( zeropad2(x)[h+di,w+dj] + w[b,c,di,dj] ) + bias[b,c]
// x [8,128,128,128] f32. stride=1, pad=2.
//
// R9: fp16 HADD2/HMAX2 tree fold + SMEM-STAGED fp16 TILE.
//   Block = half plane (64 output rows): stages 68 input rows x 132 cols
//   (2-col zero halo each side) as fp16 into an 18.5KB smem tile, zero-
//   padded. Hot loop then has ZERO predicates and ZERO global loads:
//   6 LDS.64 (lat 29) + 5 PRMT per input row, then the fold.
//   Thread = 8 output cols x 8 output rows; 5 in-flight acc rows.
//   Bias folded into fp16 weights (w+b in fp32, one rounding).
//   Zero padding: OOB gives x=0 (reference zero-pads BEFORE +w).

#define H_DIM 128
#define W_DIM 128
#define TROWS 68            // 64 output rows + 2 halo each side
#define TPITCH 136          // halves per tile row (4 halo + 128 + pad), 272B

__device__ __forceinline__ unsigned h2u(__half2 v) {
    return *reinterpret_cast<unsigned*>(&v);
}
__device__ __forceinline__ __half2 u2h(unsigned v) {
    return *reinterpret_cast<__half2*>(&v);
}
// (a.y, b.x) — one PRMT
__device__ __forceinline__ __half2 h2shift(__half2 a, __half2 b) {
    return u2h(__byte_perm(h2u(a), h2u(b), 0x5432));
}

__global__ __launch_bounds__(128, 8)
void dilation_kernel(const float* __restrict__ x,
                     const float* __restrict__ wgt,
                     const float* __restrict__ bias,
                     float* __restrict__ out) {
    __shared__ __half2 s_tile[TROWS * TPITCH / 2];   // 18496 B

    const int blk   = blockIdx.x;            // 0..2047
    const int plane = blk >> 1;              // b*C + c
    const int half  = blk & 1;
    const int tid   = threadIdx.x;
    const int cg    = tid & 15;              // column group 0..15 (8 cols)
    const int strip = tid >> 4;              // 0..7 (8 rows each)
    const int colbase = cg << 3;

    const float* __restrict__ xpl = x   + (size_t)plane * (H_DIM * W_DIM);
    float*       __restrict__ op  = out + (size_t)plane * (H_DIM * W_DIM) + colbase;
    const float* __restrict__ wp  = wgt + plane * 25;
    const float b = __ldg(&bias[plane]);

    // fp16 weights with bias folded (single rounding of w+b)
    __half2 wh[25];
#pragma unroll
    for (int k = 0; k < 25; ++k) wh[k] = __float2half2_rn(__ldg(&wp[k]) + b);

    // ---- stage tile: zero-fill, then overwrite valid region ----
    const __half2 z2 = __floats2half2_rn(0.f, 0.f);
#pragma unroll
    for (int i = tid; i < TROWS * TPITCH / 2; i += 128) s_tile[i] = z2;
    __syncthreads();

    const int rtile0 = half * 64 - 2;        // global row of tile row 0
#pragma unroll
    for (int i = tid; i < TROWS * 32; i += 128) {
        const int row = i >> 5;
        const int g   = i & 31;              // float4 group, cols 4g..4g+3
        const int r   = rtile0 + row;
        if ((unsigned)r < (unsigned)H_DIM) {
            const float4 v = __ldg(reinterpret_cast<const float4*>(xpl + r * W_DIM + g * 4));
            const int bi = (row * TPITCH + 4 + g * 4) >> 1;  // half2 index
            s_tile[bi]     = __floats2half2_rn(v.x, v.y);
            s_tile[bi + 1] = __floats2half2_rn(v.z, v.w);
        }
    }
    __syncthreads();

    // ---- fold loop: no predicates, no global loads ----
    // thread's input tile row at step t: strip*8 + t  (t = 0..11)
    // half index of pair j (cols colbase-2+j, colbase-1+j):
    //   (strip*8+t)*TPITCH + 2 + colbase + j
    const __half* s_base = reinterpret_cast<const __half*>(s_tile)
                         + strip * 8 * TPITCH + 2 + colbase;

    __half2 acc[5][4];                       // 5 in-flight output rows x 4 pairs

#pragma unroll
    for (int t = 0; t < 12; ++t) {
        const __half* rp = s_base + t * TPITCH;

        __half2 pairs[11];
#pragma unroll
        for (int i = 0; i < 6; ++i)
            pairs[2 * i] = *reinterpret_cast<const __half2*>(rp + 2 * i);
#pragma unroll
        for (int i = 0; i < 5; ++i)
            pairs[2 * i + 1] = h2shift(pairs[2 * i], pairs[2 * i + 2]);

        // fold into in-flight outputs oh = t-di (weight row di), tree max
#pragma unroll
        for (int di = 0; di < 5; ++di) {
            const int oh = t - di;
            if (oh < 0 || oh > 7) continue;  // compile-time pruned
            __half2* a = acc[oh % 5];
            const __half2* w = &wh[di * 5];
#pragma unroll
            for (int p = 0; p < 4; ++p) {
                const __half2 m01 = __hmax2(__hadd2(pairs[2 * p],     w[0]),
                                            __hadd2(pairs[2 * p + 1], w[1]));
                const __half2 m23 = __hmax2(__hadd2(pairs[2 * p + 2], w[2]),
                                            __hadd2(pairs[2 * p + 3], w[3]));
                const __half2 m4  = __hadd2(pairs[2 * p + 4], w[4]);
                const __half2 m   = __hmax2(__hmax2(m01, m23), m4);
                a[p] = (di == 0) ? m : __hmax2(a[p], m);
            }
        }

        // output row oh = t-4 complete: convert to fp32, store (bias already in)
        if (t >= 4) {
            const int oh = t - 4;
            const __half2* a = acc[oh % 5];
            float* orow = op + (size_t)(half * 64 + strip * 8 + oh) * W_DIM;
            const float2 f0 = __half22float2(a[0]);
            const float2 f1 = __half22float2(a[1]);
            const float2 f2 = __half22float2(a[2]);
            const float2 f3 = __half22float2(a[3]);
            *reinterpret_cast<float4*>(orow)     = make_float4(f0.x, f0.y, f1.x, f1.y);
            *reinterpret_cast<float4*>(orow + 4) = make_float4(f2.x, f2.y, f3.x, f3.y);
        }
    }
}

extern "C" void kernel_launch(void* const* d_in, const int* in_sizes, int n_in,
                              void* d_out, int out_size) {
    (void)in_sizes; (void)n_in; (void)out_size;
    const float* x    = (const float*)d_in[0];   // [8,128,128,128]
    const float* wgt  = (const float*)d_in[1];   // [8,128,5,5]
    const float* bias = (const float*)d_in[2];   // [8,128]
    float* out = (float*)d_out;                  // [8,128,128,128]

    dilation_kernel<<<2048, 128>>>(x, wgt, bias, out);
}